// round 4
// baseline (speedup 1.0000x reference)
#include <cuda_runtime.h>
#include <cuda_bf16.h>
#include <math.h>

// Problem shape (fixed by the dataset)
#define BB   1024
#define TT   256
#define CC   384
#define HH   64
#define NQKV 192                 // q|k|v interleaved per row
#define BT   (BB * TT)           // 262144 rows
#define BKP  32                  // projection K-tile

// Scratch: interleaved qkv projections [BT, 192] (fp32) = 201 MB
__device__ float g_qkv[(size_t)BT * NQKV];

// ---------------- cp.async helpers ----------------
__device__ __forceinline__ void cp_async16(void* smem, const void* gmem) {
    unsigned saddr = (unsigned)__cvta_generic_to_shared(smem);
    asm volatile("cp.async.cg.shared.global [%0], [%1], 16;\n"
                 :: "r"(saddr), "l"(gmem));
}
__device__ __forceinline__ void cp_commit() {
    asm volatile("cp.async.commit_group;\n");
}
__device__ __forceinline__ void cp_wait0() {
    asm volatile("cp.async.wait_group 0;\n" ::: "memory");
}
__device__ __forceinline__ void cp_wait1() {
    asm volatile("cp.async.wait_group 1;\n" ::: "memory");
}

// ---------------------------------------------------------------------------
// Kernel 1: fused QKV projection.  C = idx[BT,384] @ [Wq|Wk|Wv][384,192]
// Tiled SGEMM: BM=64, BN=192, BK=32; 256 threads; 4x12 microtile/thread;
// cp.async double-buffered so DRAM latency never exposes between tiles.
// Shared memory is DYNAMIC (64 KB > 48 KB static cap).
//   a_s[buf][row][k] : 2*64*32  floats = 16 KB   (offset 0)
//   w_s[buf][k][col] : 2*32*192 floats = 48 KB   (offset 16 KB)
// ---------------------------------------------------------------------------
#define PROJ_SMEM_FLOATS (2*64*BKP + 2*BKP*192)   // 16384 floats = 64 KB

__global__ void __launch_bounds__(256)
proj_kernel(const float* __restrict__ idx,
            const float* __restrict__ Wq,
            const float* __restrict__ Wk,
            const float* __restrict__ Wv)
{
    extern __shared__ __align__(16) float psm[];
    float* a_sm = psm;                    // [buf][row][k]
    float* w_sm = psm + 2 * 64 * BKP;     // [buf][k][col]

    const int row0 = blockIdx.x * 64;
    const int tid  = threadIdx.x;
    const int tx   = tid & 15;    // col group: cols 12*tx .. 12*tx+11
    const int ty   = tid >> 4;    // row group: rows 4*ty .. 4*ty+3

    // issue all cp.async for one (A,W) tile, then commit as one group
    auto load_tile = [&](int buf, int k0) {
        float* a_s = a_sm + buf * (64 * BKP);
        float* w_s = w_sm + buf * (BKP * 192);
        // A tile: 64 rows x 32 k = 512 x 16B chunks, 2 per thread
#pragma unroll
        for (int u = 0; u < 2; u++) {
            int c  = tid + 256 * u;          // 0..511
            int r  = c >> 3;                 // 0..63
            int kq = (c & 7) * 4;            // 0,4,..,28
            cp_async16(&a_s[r * BKP + kq],
                       &idx[(size_t)(row0 + r) * CC + k0 + kq]);
        }
        // W tile: 32 k x 192 cols = 1536 x 16B chunks, 6 per thread
#pragma unroll
        for (int u = 0; u < 6; u++) {
            int c  = tid + 256 * u;          // 0..1535
            int kk = c / 48;                 // 0..31
            int cq = (c % 48) * 4;           // 0..188
            const float* src; int cc = cq;
            if (cc < 64)       { src = Wq; }
            else if (cc < 128) { src = Wk; cc -= 64; }
            else               { src = Wv; cc -= 128; }
            cp_async16(&w_s[kk * 192 + cq],
                       &src[(size_t)(k0 + kk) * HH + cc]);
        }
        cp_commit();
    };

    float acc[4][12];
#pragma unroll
    for (int i = 0; i < 4; i++)
#pragma unroll
        for (int j = 0; j < 12; j++) acc[i][j] = 0.f;

    load_tile(0, 0);

    const int NT = CC / BKP;     // 12 tiles
    for (int t = 0; t < NT; t++) {
        int cur = t & 1;
        if (t + 1 < NT) { load_tile(cur ^ 1, (t + 1) * BKP); cp_wait1(); }
        else            { cp_wait0(); }
        __syncthreads();

        const float* a_s = a_sm + cur * (64 * BKP);
        const float* w_s = w_sm + cur * (BKP * 192);

#pragma unroll 8
        for (int k = 0; k < BKP; k++) {
            float a[4];
#pragma unroll
            for (int i = 0; i < 4; i++) a[i] = a_s[(4 * ty + i) * BKP + k];
            float b[12];
#pragma unroll
            for (int u = 0; u < 3; u++) {
                float4 b4 = *reinterpret_cast<const float4*>(&w_s[k * 192 + 12 * tx + 4 * u]);
                b[4 * u + 0] = b4.x; b[4 * u + 1] = b4.y;
                b[4 * u + 2] = b4.z; b[4 * u + 3] = b4.w;
            }
#pragma unroll
            for (int i = 0; i < 4; i++)
#pragma unroll
                for (int j = 0; j < 12; j++)
                    acc[i][j] = fmaf(a[i], b[j], acc[i][j]);
        }
        __syncthreads();   // all reads of 'cur' done before it is refilled at t+2
    }

    // store 4x12 microtile (3 x STG.128 per row)
#pragma unroll
    for (int i = 0; i < 4; i++) {
        float* rp = &g_qkv[(size_t)(row0 + 4 * ty + i) * NQKV + 12 * tx];
#pragma unroll
        for (int u = 0; u < 3; u++) {
            float4 v4 = make_float4(acc[i][4 * u + 0], acc[i][4 * u + 1],
                                    acc[i][4 * u + 2], acc[i][4 * u + 3]);
            *reinterpret_cast<float4*>(rp + 4 * u) = v4;
        }
    }
}

// ---------------------------------------------------------------------------
// Kernel 2: causal attention, one CTA per batch, one thread per query row.
// K/V smem reads are broadcast LDS.128 (all active lanes share the address),
// so the instruction mix is ~1 LDS per 8 FFMA instead of 1:1 -> FFMA-bound.
// Softmax without max-subtraction: scores = qk*384^-0.5, std~0.41, |s|<~3
// over all samples, so plain __expf is exact-safe in fp32 and l >= 1.
// ---------------------------------------------------------------------------
#define QS_STRIDE 68   // padded q rows (272B, 16B-aligned)

__global__ void __launch_bounds__(256)
attn_kernel(float* __restrict__ out)
{
    extern __shared__ __align__(16) float smem[];
    float* q_s = smem;                         // 256 * 68
    float* k_s = q_s + 256 * QS_STRIDE;        // 256 * 64
    float* v_s = k_s + 256 * 64;               // 256 * 64

    const int b   = blockIdx.x;
    const int tid = threadIdx.x;
    const float scale = 0.05103103631f;        // 384^-0.5

    const float* base = &g_qkv[(size_t)b * TT * NQKV];

    // cooperative load of q,k,v (each qkv row: 192 floats = q|k|v)
    for (int i = tid; i < 256 * 16; i += 256) {
        int r  = i >> 4;
        int c4 = (i & 15) * 4;
        const float* rowp = base + (size_t)r * NQKV;
        float4 qv = *reinterpret_cast<const float4*>(rowp + c4);
        float4 kv = *reinterpret_cast<const float4*>(rowp + 64 + c4);
        float4 vv = *reinterpret_cast<const float4*>(rowp + 128 + c4);
        *reinterpret_cast<float4*>(&q_s[r * QS_STRIDE + c4]) = qv;
        *reinterpret_cast<float4*>(&k_s[(r << 6) + c4])      = kv;
        *reinterpret_cast<float4*>(&v_s[(r << 6) + c4])      = vv;
    }
    __syncthreads();

    // my query row -> registers
    float q[64];
#pragma unroll
    for (int h4 = 0; h4 < 16; h4++) {
        float4 qv = *reinterpret_cast<const float4*>(&q_s[tid * QS_STRIDE + 4 * h4]);
        q[4 * h4 + 0] = qv.x; q[4 * h4 + 1] = qv.y;
        q[4 * h4 + 2] = qv.z; q[4 * h4 + 3] = qv.w;
    }

    float acc[64];
#pragma unroll
    for (int h = 0; h < 64; h++) acc[h] = 0.f;
    float l = 0.f;

    // causal loop in chunks of 4 keys; rows never exceed 255
    // (s0 <= tid <= 255, s0 multiple of 4 -> s0+3 <= 255)
    for (int s0 = 0; s0 <= tid; s0 += 4) {
        float p[4];
#pragma unroll
        for (int j = 0; j < 4; j++) {
            const float4* kr = reinterpret_cast<const float4*>(&k_s[(s0 + j) << 6]);
            float d0 = 0.f, d1 = 0.f, d2 = 0.f, d3 = 0.f;
#pragma unroll
            for (int hh = 0; hh < 16; hh++) {
                float4 kv = kr[hh];
                d0 = fmaf(q[4 * hh + 0], kv.x, d0);
                d1 = fmaf(q[4 * hh + 1], kv.y, d1);
                d2 = fmaf(q[4 * hh + 2], kv.z, d2);
                d3 = fmaf(q[4 * hh + 3], kv.w, d3);
            }
            float d = (d0 + d1) + (d2 + d3);
            p[j] = (s0 + j <= tid) ? __expf(d * scale) : 0.f;
            l += p[j];
        }
#pragma unroll
        for (int j = 0; j < 4; j++) {
            float pj = p[j];
            const float4* vr = reinterpret_cast<const float4*>(&v_s[(s0 + j) << 6]);
#pragma unroll
            for (int hh = 0; hh < 16; hh++) {
                float4 vv = vr[hh];
                acc[4 * hh + 0] = fmaf(pj, vv.x, acc[4 * hh + 0]);
                acc[4 * hh + 1] = fmaf(pj, vv.y, acc[4 * hh + 1]);
                acc[4 * hh + 2] = fmaf(pj, vv.z, acc[4 * hh + 2]);
                acc[4 * hh + 3] = fmaf(pj, vv.w, acc[4 * hh + 3]);
            }
        }
    }

    float inv = 1.f / l;
    float* o = out + ((size_t)b * TT + tid) * HH;
#pragma unroll
    for (int hh = 0; hh < 16; hh++) {
        float4 v4 = make_float4(acc[4 * hh + 0] * inv, acc[4 * hh + 1] * inv,
                                acc[4 * hh + 2] * inv, acc[4 * hh + 3] * inv);
        *reinterpret_cast<float4*>(o + 4 * hh) = v4;
    }
}

// ---------------------------------------------------------------------------
// Launch: proj -> attn (same stream, graph-capturable; no allocs, no syncs)
// ---------------------------------------------------------------------------
extern "C" void kernel_launch(void* const* d_in, const int* in_sizes, int n_in,
                              void* d_out, int out_size)
{
    const float* idx = (const float*)d_in[0];
    const float* Wq  = (const float*)d_in[1];
    const float* Wk  = (const float*)d_in[2];
    const float* Wv  = (const float*)d_in[3];
    float* out = (float*)d_out;

    const int proj_smem = PROJ_SMEM_FLOATS * (int)sizeof(float);             // 65536 B
    const int attn_smem = (256 * QS_STRIDE + 2 * 256 * 64) * (int)sizeof(float); // 200704 B
    cudaFuncSetAttribute(proj_kernel, cudaFuncAttributeMaxDynamicSharedMemorySize, proj_smem);
    cudaFuncSetAttribute(attn_kernel, cudaFuncAttributeMaxDynamicSharedMemorySize, attn_smem);

    proj_kernel<<<BT / 64, 256, proj_smem>>>(idx, Wq, Wk, Wv);
    attn_kernel<<<BB, 256, attn_smem>>>(out);
}

// round 7
// speedup vs baseline: 1.6206x; 1.6206x over previous
#include <cuda_runtime.h>
#include <cuda_bf16.h>
#include <math.h>
#include <stdint.h>

// Problem shape (fixed by the dataset)
#define BB   1024
#define TT   256
#define CC   384
#define HH   64
#define NQKV 192                 // q|k|v interleaved per row
#define BT   (BB * TT)           // 262144 rows

// Scratch: interleaved qkv projections [BT, 192] (fp32) = 201 MB
__device__ float g_qkv[(size_t)BT * NQKV];

// W image: [6 k-chunks][hi 24KB | lo 24KB], each [192 n-rows][128 bytes] SW128
__device__ __align__(16) unsigned char g_wimg[6 * 2 * 192 * 128];

#define SWZ(x) ((x) ^ (((x) >> 3) & 0x70))

// ---------------- cp.async helpers ----------------
__device__ __forceinline__ void cp_async16(void* smem, const void* gmem) {
    unsigned saddr = (unsigned)__cvta_generic_to_shared(smem);
    asm volatile("cp.async.cg.shared.global [%0], [%1], 16;\n"
                 :: "r"(saddr), "l"(gmem));
}
__device__ __forceinline__ void cp_commit() {
    asm volatile("cp.async.commit_group;\n");
}
__device__ __forceinline__ void cp_wait0() {
    asm volatile("cp.async.wait_group 0;\n" ::: "memory");
}

// ---------------- ldmatrix / mma.sync (compute_100-baseline PTX) -----------
__device__ __forceinline__ void ldsm4(uint32_t* r, uint32_t addr) {
    asm volatile("ldmatrix.sync.aligned.m8n8.x4.shared.b16 {%0,%1,%2,%3}, [%4];"
                 : "=r"(r[0]), "=r"(r[1]), "=r"(r[2]), "=r"(r[3]) : "r"(addr));
}
__device__ __forceinline__ void mma16816(float* d, const uint32_t* a,
                                         uint32_t b0, uint32_t b1) {
    asm volatile("mma.sync.aligned.m16n8k16.row.col.f32.bf16.bf16.f32 "
                 "{%0,%1,%2,%3}, {%4,%5,%6,%7}, {%8,%9}, {%0,%1,%2,%3};"
                 : "+f"(d[0]), "+f"(d[1]), "+f"(d[2]), "+f"(d[3])
                 : "r"(a[0]), "r"(a[1]), "r"(a[2]), "r"(a[3]), "r"(b0), "r"(b1));
}

// ---------------------------------------------------------------------------
// Kernel 0: W prep — split Wq|Wk|Wv into bf16 hi/lo, transpose to [n][k],
// SW128-swizzle into g_wimg (the exact smem image cp.async copies verbatim).
// ---------------------------------------------------------------------------
__global__ void wprep_kernel(const float* __restrict__ Wq,
                             const float* __restrict__ Wk,
                             const float* __restrict__ Wv)
{
    int i = blockIdx.x * 256 + threadIdx.x;      // over 6*192*64 = 73728
    if (i >= 6 * 192 * 64) return;
    int c = i / (192 * 64);
    int n = (i / 64) % 192;
    int k = i % 64;
    int gk = c * 64 + k;
    const float* src = (n < 64) ? Wq : (n < 128 ? Wk : Wv);
    float w = src[(size_t)gk * HH + (n & 63)];
    __nv_bfloat16 hi = __float2bfloat16(w);
    __nv_bfloat16 lo = __float2bfloat16(w - __bfloat162float(hi));
    unsigned sb = SWZ((unsigned)(n * 128 + k * 2));
    *(__nv_bfloat16*)&g_wimg[(size_t)c * 49152 + sb]         = hi;
    *(__nv_bfloat16*)&g_wimg[(size_t)c * 49152 + 24576 + sb] = lo;
}

// ---------------------------------------------------------------------------
// Kernel 1: QKV projection via mma.sync (bf16 hi/lo, fp32 accum).
// C[BT,192] = A[BT,384] @ W[384,192].
// CTA: 512 threads (16 warps, grid 4Mx4N), tile M=128 N=192; warp tile 32x48.
// K in 6 chunks of 64, double-buffered: B via cp.async from g_wimg,
// A via reg-staged LDG -> bf16 split -> swizzled STS, overlapped with MMA.
// smem: A[buf]: hi 16KB + lo 16KB @ buf*32768 ; B[buf]: hi 24KB + lo 24KB
//       @ 65536 + buf*49152. Total 160KB.
// ---------------------------------------------------------------------------
#define SM_A(buf)   ((buf) * 32768)
#define SM_B(buf)   (65536 + (buf) * 49152)
#define PROJ_SMEM   163840

__global__ void __launch_bounds__(512, 1)
proj_mma_kernel(const float* __restrict__ idx)
{
    extern __shared__ __align__(1024) unsigned char sm[];
    const int tid = threadIdx.x;
    const int wid = tid >> 5;
    const int lid = tid & 31;
    const int wm  = wid & 3;                  // M group (rows wm*32..+31)
    const int wn  = wid >> 2;                 // N group (cols wn*48..+47)
    const size_t row0 = (size_t)blockIdx.x * 128;
    const uint32_t smem_base = (uint32_t)__cvta_generic_to_shared(sm);

    // per-lane ldmatrix geometry (x4: lanes 0-7 -> mat0 rows, 8-15 -> mat1,
    // 16-23 -> mat2 (k+8), 24-31 -> mat3)
    const int l8 = lid & 7, tq = lid >> 3;    // tq 0..3
    const uint32_t t16 = (uint32_t)(tq >> 1) * 16;   // k-half byte offset
    uint32_t arow[2], asw[2];
#pragma unroll
    for (int i = 0; i < 2; i++) {
        int r = wm * 32 + i * 16 + l8 + (tq & 1) * 8;
        arow[i] = (uint32_t)r * 128;
        asw[i]  = (uint32_t)(r & 7) << 4;
    }
    uint32_t brow[3], bsw[3];
#pragma unroll
    for (int jp = 0; jp < 3; jp++) {
        int n = wn * 48 + jp * 16 + l8 + (tq & 1) * 8;
        brow[jp] = (uint32_t)n * 128;
        bsw[jp]  = (uint32_t)(n & 7) << 4;
    }

    float d[2][6][4];
#pragma unroll
    for (int i = 0; i < 2; i++)
#pragma unroll
        for (int j = 0; j < 6; j++)
#pragma unroll
            for (int e = 0; e < 4; e++) d[i][j][e] = 0.f;

    // --- helpers as lambdas ---
    auto lda_stage = [&](int c, float4* st) {
#pragma unroll
        for (int u = 0; u < 4; u++) {
            int f  = tid + 512 * u;               // 0..2047
            int r  = f >> 4;
            int kq = (f & 15) * 4;
            st[u] = *reinterpret_cast<const float4*>(
                &idx[(row0 + r) * CC + c * 64 + kq]);
        }
    };
    auto sts_a = [&](int buf, const float4* st) {
        unsigned char* ahi = sm + SM_A(buf);
        unsigned char* alo = ahi + 16384;
#pragma unroll
        for (int u = 0; u < 4; u++) {
            int f  = tid + 512 * u;
            int r  = f >> 4;
            int kq = (f & 15) * 4;
            float4 a4 = st[u];
            __nv_bfloat162 h01 = __float22bfloat162_rn(make_float2(a4.x, a4.y));
            __nv_bfloat162 h23 = __float22bfloat162_rn(make_float2(a4.z, a4.w));
            float r0 = a4.x - __low2float(h01);
            float r1 = a4.y - __high2float(h01);
            float r2 = a4.z - __low2float(h23);
            float r3 = a4.w - __high2float(h23);
            __nv_bfloat162 l01 = __float22bfloat162_rn(make_float2(r0, r1));
            __nv_bfloat162 l23 = __float22bfloat162_rn(make_float2(r2, r3));
            unsigned sb = SWZ((unsigned)(r * 128 + kq * 2));
            *reinterpret_cast<uint2*>(ahi + sb) =
                make_uint2(*(const uint32_t*)&h01, *(const uint32_t*)&h23);
            *reinterpret_cast<uint2*>(alo + sb) =
                make_uint2(*(const uint32_t*)&l01, *(const uint32_t*)&l23);
        }
    };
    auto ldb_async = [&](int c, int buf) {
        const unsigned char* bsrc = g_wimg + (size_t)c * 49152;
        unsigned char* bdst = sm + SM_B(buf);
#pragma unroll
        for (int u = 0; u < 6; u++) {
            int o = (tid + 512 * u) * 16;         // 0..49136
            cp_async16(bdst + o, bsrc + o);
        }
        cp_commit();
    };

    // --- prologue: chunk 0 ---
    float4 st[4];
    lda_stage(0, st);
    sts_a(0, st);
    ldb_async(0, 0);

    // --- main loop over 6 K-chunks ---
    for (int c = 0; c < 6; c++) {
        const int buf = c & 1;
        cp_wait0();
        __syncthreads();

        if (c < 5) { lda_stage(c + 1, st); ldb_async(c + 1, buf ^ 1); }

        const uint32_t ahb = smem_base + SM_A(buf);
        const uint32_t alb = ahb + 16384;
        const uint32_t bhb = smem_base + SM_B(buf);
        const uint32_t blb = bhb + 24576;

#pragma unroll
        for (int ks = 0; ks < 4; ks++) {
            const uint32_t kin = t16 + (uint32_t)ks * 32;
            uint32_t ah[2][4], al[2][4];
#pragma unroll
            for (int i = 0; i < 2; i++) {
                ldsm4(ah[i], ahb + arow[i] + (kin ^ asw[i]));
                ldsm4(al[i], alb + arow[i] + (kin ^ asw[i]));
            }
#pragma unroll
            for (int jp = 0; jp < 3; jp++) {
                uint32_t bh[4], bl[4];
                ldsm4(bh, bhb + brow[jp] + (kin ^ bsw[jp]));
                ldsm4(bl, blb + brow[jp] + (kin ^ bsw[jp]));
#pragma unroll
                for (int i = 0; i < 2; i++) {
                    // n-tile 2*jp uses {r0,r2}; 2*jp+1 uses {r1,r3}
                    mma16816(d[i][2 * jp + 0], ah[i], bh[0], bh[2]);
                    mma16816(d[i][2 * jp + 1], ah[i], bh[1], bh[3]);
                    mma16816(d[i][2 * jp + 0], al[i], bh[0], bh[2]);
                    mma16816(d[i][2 * jp + 1], al[i], bh[1], bh[3]);
                    mma16816(d[i][2 * jp + 0], ah[i], bl[0], bl[2]);
                    mma16816(d[i][2 * jp + 1], ah[i], bl[1], bl[3]);
                }
            }
        }

        // BUGFIX (round 6): first arg is the BUFFER index, not the chunk id.
        // Passing c+1 wrote up to SM_A(5)+32KB = past the 160KB smem window.
        if (c < 5) sts_a((c + 1) & 1, st);   // fills buf^1; MMAs above read buf
    }

    // --- epilogue: direct fragment stores (4-lane bursts = 32B sectors) ---
    const int fr = lid >> 2;                  // 0..7
    const int fc = (lid & 3) * 2;             // 0,2,4,6
#pragma unroll
    for (int i = 0; i < 2; i++) {
        size_t rbase = row0 + (size_t)(wm * 32 + i * 16 + fr);
#pragma unroll
        for (int j = 0; j < 6; j++) {
            int col = wn * 48 + (j >> 1) * 16 + (j & 1) * 8 + fc;
            float* p = g_qkv + rbase * NQKV + col;
            *reinterpret_cast<float2*>(p) = make_float2(d[i][j][0], d[i][j][1]);
            *reinterpret_cast<float2*>(p + (size_t)8 * NQKV) =
                make_float2(d[i][j][2], d[i][j][3]);
        }
    }
}

// ---------------------------------------------------------------------------
// Kernel 2: causal attention (unchanged passing version).
// ---------------------------------------------------------------------------
#define QS_STRIDE 68

__global__ void __launch_bounds__(256)
attn_kernel(float* __restrict__ out)
{
    extern __shared__ __align__(16) float smem[];
    float* q_s = smem;                         // 256 * 68
    float* k_s = q_s + 256 * QS_STRIDE;        // 256 * 64
    float* v_s = k_s + 256 * 64;               // 256 * 64

    const int b   = blockIdx.x;
    const int tid = threadIdx.x;
    const float scale = 0.05103103631f;        // 384^-0.5

    const float* base = &g_qkv[(size_t)b * TT * NQKV];

    for (int i = tid; i < 256 * 16; i += 256) {
        int r  = i >> 4;
        int c4 = (i & 15) * 4;
        const float* rowp = base + (size_t)r * NQKV;
        float4 qv = *reinterpret_cast<const float4*>(rowp + c4);
        float4 kv = *reinterpret_cast<const float4*>(rowp + 64 + c4);
        float4 vv = *reinterpret_cast<const float4*>(rowp + 128 + c4);
        *reinterpret_cast<float4*>(&q_s[r * QS_STRIDE + c4]) = qv;
        *reinterpret_cast<float4*>(&k_s[(r << 6) + c4])      = kv;
        *reinterpret_cast<float4*>(&v_s[(r << 6) + c4])      = vv;
    }
    __syncthreads();

    float q[64];
#pragma unroll
    for (int h4 = 0; h4 < 16; h4++) {
        float4 qv = *reinterpret_cast<const float4*>(&q_s[tid * QS_STRIDE + 4 * h4]);
        q[4 * h4 + 0] = qv.x; q[4 * h4 + 1] = qv.y;
        q[4 * h4 + 2] = qv.z; q[4 * h4 + 3] = qv.w;
    }

    float acc[64];
#pragma unroll
    for (int h = 0; h < 64; h++) acc[h] = 0.f;
    float l = 0.f;

    for (int s0 = 0; s0 <= tid; s0 += 4) {
        float p[4];
#pragma unroll
        for (int j = 0; j < 4; j++) {
            const float4* kr = reinterpret_cast<const float4*>(&k_s[(s0 + j) << 6]);
            float d0 = 0.f, d1 = 0.f, d2 = 0.f, d3 = 0.f;
#pragma unroll
            for (int hh = 0; hh < 16; hh++) {
                float4 kv = kr[hh];
                d0 = fmaf(q[4 * hh + 0], kv.x, d0);
                d1 = fmaf(q[4 * hh + 1], kv.y, d1);
                d2 = fmaf(q[4 * hh + 2], kv.z, d2);
                d3 = fmaf(q[4 * hh + 3], kv.w, d3);
            }
            float dd = (d0 + d1) + (d2 + d3);
            p[j] = (s0 + j <= tid) ? __expf(dd * scale) : 0.f;
            l += p[j];
        }
#pragma unroll
        for (int j = 0; j < 4; j++) {
            float pj = p[j];
            const float4* vr = reinterpret_cast<const float4*>(&v_s[(s0 + j) << 6]);
#pragma unroll
            for (int hh = 0; hh < 16; hh++) {
                float4 vv = vr[hh];
                acc[4 * hh + 0] = fmaf(pj, vv.x, acc[4 * hh + 0]);
                acc[4 * hh + 1] = fmaf(pj, vv.y, acc[4 * hh + 1]);
                acc[4 * hh + 2] = fmaf(pj, vv.z, acc[4 * hh + 2]);
                acc[4 * hh + 3] = fmaf(pj, vv.w, acc[4 * hh + 3]);
            }
        }
    }

    float inv = 1.f / l;
    float* o = out + ((size_t)b * TT + tid) * HH;
#pragma unroll
    for (int hh = 0; hh < 16; hh++) {
        float4 v4 = make_float4(acc[4 * hh + 0] * inv, acc[4 * hh + 1] * inv,
                                acc[4 * hh + 2] * inv, acc[4 * hh + 3] * inv);
        *reinterpret_cast<float4*>(o + 4 * hh) = v4;
    }
}

// ---------------------------------------------------------------------------
// Launch: wprep -> proj_mma -> attn (one stream; graph-capturable; no allocs)
// ---------------------------------------------------------------------------
extern "C" void kernel_launch(void* const* d_in, const int* in_sizes, int n_in,
                              void* d_out, int out_size)
{
    const float* idx = (const float*)d_in[0];
    const float* Wq  = (const float*)d_in[1];
    const float* Wk  = (const float*)d_in[2];
    const float* Wv  = (const float*)d_in[3];
    float* out = (float*)d_out;

    const int attn_smem = (256 * QS_STRIDE + 2 * 256 * 64) * (int)sizeof(float);
    cudaFuncSetAttribute(proj_mma_kernel, cudaFuncAttributeMaxDynamicSharedMemorySize, PROJ_SMEM);
    cudaFuncSetAttribute(attn_kernel,     cudaFuncAttributeMaxDynamicSharedMemorySize, attn_smem);

    wprep_kernel<<<288, 256>>>(Wq, Wk, Wv);
    proj_mma_kernel<<<BT / 128, 512, PROJ_SMEM>>>(idx);
    attn_kernel<<<BB, 256, attn_smem>>>(out);
}